// round 1
// baseline (speedup 1.0000x reference)
#include <cuda_runtime.h>
#include <cstdint>

#define N_VOX 200000
#define CCH   64
#define PP    65536
#define NOFF  26
#define EPSV  1e-5f

// Scratch (allocation-free rule: __device__ globals)
__device__ float g_h1[(size_t)N_VOX * CCH];
__device__ float g_h2[(size_t)N_VOX * CCH];
__device__ float g_stats[256];  // [0:64] sum1 [64:128] sq1 [128:192] sum2 [192:256] sq2
__device__ float g_coef[256];   // [0:64] scale1 [64:128] shift1 [128:192] scale2 [192:256] shift2

// ---------------------------------------------------------------------------
// conv kernel: 128 threads, 64 rows/pairs per block.
//   SCATTER=true : block = (pair tile of 64, offset k=blockIdx.y), gathers x rows,
//                  computes x_row @ W_k, red.global.add.v4 into H[out_row].
//   SCATTER=false: center tap, rows = blockIdx.x*64.., direct float4 store.
// Thread mapping: og = t&15 -> 4 contiguous out channels; pg = t>>4 -> 8 pairs.
// ---------------------------------------------------------------------------
template <bool SCATTER>
__global__ __launch_bounds__(128)
void conv_kernel(const float* __restrict__ x,
                 const float* __restrict__ W,      // [27,64,64]
                 const int*   __restrict__ in_map, // [26,P] or null
                 const int*   __restrict__ out_map,
                 float*       __restrict__ H)
{
    __shared__ float sW[64 * 64];
    __shared__ float sX[64 * 66];   // 66-float stride: conflict-free inner LDS
    __shared__ int   s_in[64];
    __shared__ int   s_out[64];

    const int t = threadIdx.x;
    const int base = blockIdx.x * 64;
    const float* Wk;

    if (SCATTER) {
        const int k = blockIdx.y;
        Wk = W + (size_t)(k < 13 ? k : k + 1) * 4096;
        if (t < 64)       s_in[t]       = in_map[(size_t)k * PP + base + t];
        else if (t < 128) s_out[t - 64] = out_map[(size_t)k * PP + base + (t - 64)];
    } else {
        Wk = W + (size_t)13 * 4096;
    }
    __syncthreads();

    if (SCATTER && s_in[0] >= N_VOX) return;   // sentinel-only tile (sentinels are tail-packed)

    // Stage W_k (16 KB)
    const float4* W4  = reinterpret_cast<const float4*>(Wk);
    float4*       sW4 = reinterpret_cast<float4*>(sW);
#pragma unroll
    for (int i = 0; i < 8; i++) sW4[t + i * 128] = W4[t + i * 128];

    // Stage 64 x rows (gathered if SCATTER), row stride 33 float2 (=66 floats)
    float2*       sX2 = reinterpret_cast<float2*>(sX);
    const float2* x2  = reinterpret_cast<const float2*>(x);
#pragma unroll
    for (int i = 0; i < 16; i++) {
        int idx = t + i * 128;            // 0..2047
        int pr  = idx >> 5;               // pair/row in tile
        int c2  = idx & 31;               // float2 column
        int row = SCATTER ? s_in[pr] : (base + pr);
        float2 v = make_float2(0.f, 0.f);
        if (row < N_VOX) v = x2[(size_t)row * 32 + c2];
        sX2[pr * 33 + c2] = v;
    }
    __syncthreads();

    const int og = t & 15;   // out group: channels [4*og, 4*og+4)
    const int pg = t >> 4;   // pair group: pairs [8*pg, 8*pg+8)

    float4 acc[8];
#pragma unroll
    for (int q = 0; q < 8; q++) acc[q] = make_float4(0.f, 0.f, 0.f, 0.f);

    const float* sXp = sX + pg * 8 * 66;
#pragma unroll 8
    for (int c = 0; c < 64; c++) {
        float4 w = sW4[c * 16 + og];
#pragma unroll
        for (int q = 0; q < 8; q++) {
            float xv = sXp[q * 66 + c];
            acc[q].x = fmaf(xv, w.x, acc[q].x);
            acc[q].y = fmaf(xv, w.y, acc[q].y);
            acc[q].z = fmaf(xv, w.z, acc[q].z);
            acc[q].w = fmaf(xv, w.w, acc[q].w);
        }
    }

#pragma unroll
    for (int q = 0; q < 8; q++) {
        int pr = pg * 8 + q;
        if (SCATTER) {
            int o = s_out[pr];
            if (o < N_VOX) {
                float* p = H + (size_t)o * 64 + og * 4;
                asm volatile("red.global.add.v4.f32 [%0], {%1,%2,%3,%4};"
                             :: "l"(p), "f"(acc[q].x), "f"(acc[q].y),
                                "f"(acc[q].z), "f"(acc[q].w)
                             : "memory");
            }
        } else {
            int row = base + pr;
            if (row < N_VOX)
                reinterpret_cast<float4*>(H + (size_t)row * 64)[og] = acc[q];
        }
    }
}

// ---------------------------------------------------------------------------
__global__ void zero_stats_kernel() { g_stats[threadIdx.x] = 0.f; }

__global__ void stats_kernel(const float* __restrict__ h, int statoff)
{
    const int t = threadIdx.x;          // 256
    const int ch = t & 63;
    const int g  = t >> 6;              // 0..3
    float s = 0.f, sq = 0.f;
    for (int row = blockIdx.x * 4 + g; row < N_VOX; row += gridDim.x * 4) {
        float v = h[(size_t)row * 64 + ch];
        s += v; sq += v * v;
    }
    __shared__ float sh[2][4][64];
    sh[0][g][ch] = s;
    sh[1][g][ch] = sq;
    __syncthreads();
    if (t < 64) {
        float ss = sh[0][0][t] + sh[0][1][t] + sh[0][2][t] + sh[0][3][t];
        atomicAdd(&g_stats[statoff + t], ss);
    } else if (t < 128) {
        int c = t - 64;
        float qq = sh[1][0][c] + sh[1][1][c] + sh[1][2][c] + sh[1][3][c];
        atomicAdd(&g_stats[statoff + 64 + c], qq);
    }
}

__global__ void finalize_stats_kernel(const float* __restrict__ gamma,
                                      const float* __restrict__ beta,
                                      int statoff, int coefoff)
{
    const int c = threadIdx.x;  // 64
    const float inv_n = 1.0f / (float)N_VOX;
    float mu  = g_stats[statoff + c] * inv_n;
    float var = g_stats[statoff + 64 + c] * inv_n - mu * mu;
    float sc  = gamma[c] * rsqrtf(var + EPSV);
    g_coef[coefoff + c]      = sc;
    g_coef[coefoff + 64 + c] = beta[c] - mu * sc;
}

// in-place BN + ReLU on h (float4 granularity)
__global__ void bnrelu_kernel(float* __restrict__ h, int coefoff)
{
    int k = blockIdx.x * blockDim.x + threadIdx.x;   // float4 index
    if (k >= N_VOX * 16) return;
    int cb = (k & 15) * 4;
    float4 v = reinterpret_cast<float4*>(h)[k];
    float s0 = g_coef[coefoff + cb + 0], b0 = g_coef[coefoff + 64 + cb + 0];
    float s1 = g_coef[coefoff + cb + 1], b1 = g_coef[coefoff + 64 + cb + 1];
    float s2 = g_coef[coefoff + cb + 2], b2 = g_coef[coefoff + 64 + cb + 2];
    float s3 = g_coef[coefoff + cb + 3], b3 = g_coef[coefoff + 64 + cb + 3];
    v.x = fmaxf(fmaf(v.x, s0, b0), 0.f);
    v.y = fmaxf(fmaf(v.y, s1, b1), 0.f);
    v.z = fmaxf(fmaf(v.z, s2, b2), 0.f);
    v.w = fmaxf(fmaf(v.w, s3, b3), 0.f);
    reinterpret_cast<float4*>(h)[k] = v;
}

// out = relu(bn2(h2) + x)
__global__ void final_kernel(const float* __restrict__ h2,
                             const float* __restrict__ x,
                             float* __restrict__ out, int coefoff)
{
    int k = blockIdx.x * blockDim.x + threadIdx.x;
    if (k >= N_VOX * 16) return;
    int cb = (k & 15) * 4;
    float4 v = reinterpret_cast<const float4*>(h2)[k];
    float4 r = reinterpret_cast<const float4*>(x)[k];
    float s0 = g_coef[coefoff + cb + 0], b0 = g_coef[coefoff + 64 + cb + 0];
    float s1 = g_coef[coefoff + cb + 1], b1 = g_coef[coefoff + 64 + cb + 1];
    float s2 = g_coef[coefoff + cb + 2], b2 = g_coef[coefoff + 64 + cb + 2];
    float s3 = g_coef[coefoff + cb + 3], b3 = g_coef[coefoff + 64 + cb + 3];
    v.x = fmaxf(fmaf(v.x, s0, b0) + r.x, 0.f);
    v.y = fmaxf(fmaf(v.y, s1, b1) + r.y, 0.f);
    v.z = fmaxf(fmaf(v.z, s2, b2) + r.z, 0.f);
    v.w = fmaxf(fmaf(v.w, s3, b3) + r.w, 0.f);
    reinterpret_cast<float4*>(out)[k] = v;
}

// ---------------------------------------------------------------------------
extern "C" void kernel_launch(void* const* d_in, const int* in_sizes, int n_in,
                              void* d_out, int out_size)
{
    const float* x      = (const float*)d_in[0];
    const float* W1     = (const float*)d_in[1];
    const float* gamma1 = (const float*)d_in[2];
    const float* beta1  = (const float*)d_in[3];
    const float* W2     = (const float*)d_in[4];
    const float* gamma2 = (const float*)d_in[5];
    const float* beta2  = (const float*)d_in[6];
    const int*   in_map = (const int*)d_in[7];
    const int*   out_map= (const int*)d_in[8];
    float*       out    = (float*)d_out;

    float* h1;  cudaGetSymbolAddress((void**)&h1, g_h1);
    float* h2;  cudaGetSymbolAddress((void**)&h2, g_h2);

    const dim3 scat_grid(PP / 64, NOFF);
    const int  center_blocks = (N_VOX + 63) / 64;
    const int  ew_blocks     = (N_VOX * 16 + 255) / 256;

    zero_stats_kernel<<<1, 256>>>();

    // conv1
    conv_kernel<false><<<center_blocks, 128>>>(x, W1, nullptr, nullptr, h1);
    conv_kernel<true ><<<scat_grid,     128>>>(x, W1, in_map, out_map, h1);
    stats_kernel<<<1024, 256>>>(h1, 0);
    finalize_stats_kernel<<<1, 64>>>(gamma1, beta1, 0, 0);
    bnrelu_kernel<<<ew_blocks, 256>>>(h1, 0);

    // conv2
    conv_kernel<false><<<center_blocks, 128>>>(h1, W2, nullptr, nullptr, h2);
    conv_kernel<true ><<<scat_grid,     128>>>(h1, W2, in_map, out_map, h2);
    stats_kernel<<<1024, 256>>>(h2, 128);
    finalize_stats_kernel<<<1, 64>>>(gamma2, beta2, 128, 128);

    // bn2 + residual + relu -> d_out
    final_kernel<<<ew_blocks, 256>>>(h2, x, out, 128);
}